// round 4
// baseline (speedup 1.0000x reference)
#include <cuda_runtime.h>

#define IN_NODES  1152
#define OUT_NODES 10
#define IN_DIM    8
#define OUT_DIM   16
#define BATCH     256
#define COLS      160
#define KTOT      (IN_NODES * IN_DIM)     // 9216
#define ISPLIT    144
#define CPB       8
#define NTHR      640

typedef unsigned long long u64;

// packed f32x2 FMA: acc.{lo,hi} += a.{lo,hi} * b.{lo,hi}  (b64 regs, "l" constraint)
#define FMA2(acc, a, b) asm("fma.rn.f32x2 %0, %1, %2, %0;" : "+l"(acc) : "l"(a), "l"(b))

__device__ __forceinline__ float f2sum(u64 d) {
    float lo, hi;
    asm("mov.b64 {%0,%1}, %2;" : "=f"(lo), "=f"(hi) : "l"(d));
    return lo + hi;
}

// ---------------- device scratch ----------------
__device__ float g_xT   [KTOT * BATCH];            // x transposed [ik][b]
__device__ float g_spart[ISPLIT * COLS * BATCH];   // s partials [grp][col][b]
__device__ float g_vB   [BATCH * COLS];            // v batch-major [b][col]
__device__ float g_b    [IN_NODES * OUT_NODES];    // routing logits

// ---------------- transpose x [256][9216] -> xT [9216][256] ----------------
__global__ void transpose_x_kernel(const float* __restrict__ x) {
    __shared__ float tile[32][33];
    int ik0 = blockIdx.x * 32;
    int b0  = blockIdx.y * 32;
    int tx = threadIdx.x, ty = threadIdx.y;
#pragma unroll
    for (int r = 0; r < 32; r += 8)
        tile[ty + r][tx] = x[(size_t)(b0 + ty + r) * KTOT + ik0 + tx];
    __syncthreads();
#pragma unroll
    for (int r = 0; r < 32; r += 8)
        g_xT[(size_t)(ik0 + ty + r) * BATCH + b0 + tx] = tile[tx][ty + r];
}

// ---------------- fused: b-update + softmax + s-GEMM (f32x2 packed) ----------------
// grid 144, 640 threads. Block owns capsules [i0,i0+8), full batch.
// smem: phase A {vs[160][34], xs[8][8][32]} / phase B {ws[10240], xb2[8][4][64] float2}
__global__ __launch_bounds__(NTHR, 1) void f_kernel(const float* __restrict__ W, int mode) {
    extern __shared__ float sm[];
    __shared__ float bsA[2][80];
    __shared__ float brow[80];
    __shared__ float cs[80];

    const int i0  = blockIdx.x * CPB;
    const int tid = threadIdx.x;

    if (mode > 0) {
        // ===== Phase A: T[i,k,col] = sum_b xT[ik,b]*vB[b,col]; pair over b =====
        float* vs = sm;          // [160][34] (padded)
        float* xs = sm + 5440;   // [8 ic][8 k][32 b]
        const int w = tid >> 5, lane = tid & 31;
        const int ic = w & 7, kh = w >> 3;   // warps 0..15 active (kh 0/1), 16..19 idle

        u64 acc2[4][5];
#pragma unroll
        for (int kk = 0; kk < 4; ++kk)
#pragma unroll
            for (int cc = 0; cc < 5; ++cc) acc2[kk][cc] = 0ULL;

        for (int cb = 0; cb < 8; ++cb) {
            const int b0 = cb * 32;
            __syncthreads();
            for (int idx = tid; idx < 5120; idx += NTHR) {
                int b = idx / 160, col = idx - b * 160;
                vs[col * 34 + b] = g_vB[(size_t)(b0 + b) * 160 + col];
            }
            for (int idx = tid; idx < 2048; idx += NTHR) {
                int ic2 = idx >> 8, k = (idx >> 5) & 7, b = idx & 31;
                xs[idx] = g_xT[((size_t)(i0 + ic2) * 8 + k) * BATCH + b0 + b];
            }
            __syncthreads();

            if (w < 16) {
#pragma unroll 4
                for (int b2 = 0; b2 < 16; ++b2) {
                    u64 xv[4];
#pragma unroll
                    for (int kk = 0; kk < 4; ++kk)
                        xv[kk] = *(const u64*)&xs[(ic * 8 + kh * 4 + kk) * 32 + 2 * b2];
#pragma unroll
                    for (int cc = 0; cc < 5; ++cc) {
                        u64 vv = *(const u64*)&vs[(cc * 32 + lane) * 34 + 2 * b2];
#pragma unroll
                        for (int kk = 0; kk < 4; ++kk)
                            FMA2(acc2[kk][cc], xv[kk], vv);
                    }
                }
            }
        }

        // contract with W -> delta-b partials; shfl reduce over 16-lane j groups
        if (w < 16) {
#pragma unroll
            for (int cc = 0; cc < 5; ++cc) {
                int col = cc * 32 + lane;
                float4 ww = *(const float4*)(W + ((size_t)(i0 + ic) * 160 + col) * 8 + kh * 4);
                float p = ww.x * f2sum(acc2[0][cc]) + ww.y * f2sum(acc2[1][cc])
                        + ww.z * f2sum(acc2[2][cc]) + ww.w * f2sum(acc2[3][cc]);
#pragma unroll
                for (int off = 8; off; off >>= 1)
                    p += __shfl_xor_sync(0xffffffffu, p, off, 16);
                if ((lane & 15) == 0)
                    bsA[kh][ic * 10 + cc * 2 + (lane >> 4)] = p;
            }
        }
        __syncthreads();

        if (tid < 80) {
            float bn = (bsA[0][tid] + bsA[1][tid]) * (1.0f / (float)BATCH);
            if (mode == 2) bn += g_b[i0 * OUT_NODES + tid];
            g_b[i0 * OUT_NODES + tid] = bn;
            brow[tid] = bn;
        }
        __syncthreads();
        if (tid < 8) {
            float m = -1e30f;
#pragma unroll
            for (int j = 0; j < 10; ++j) m = fmaxf(m, brow[tid * 10 + j]);
            float e[10], s = 0.0f;
#pragma unroll
            for (int j = 0; j < 10; ++j) { e[j] = __expf(brow[tid * 10 + j] - m); s += e[j]; }
            float inv = 1.0f / s;
#pragma unroll
            for (int j = 0; j < 10; ++j) cs[tid * 10 + j] = e[j] * inv;
        }
        __syncthreads();
    }

    // ===== Phase B: spart[grp][col][b] = sum_{ic,k} (c*W)[i,col,k]*xT[ik,b]; pair over k =====
    float* ws   = sm;            // [8 ic][160 col][8 k] scaled W
    float* xb2f = sm + 10240;    // [8 ic][4 kp][64 b] float2 (k-interleaved)
    const int tx = tid & 15;     // 4 b each
    const int ty = tid >> 4;     // 0..39, 4 cols each

    for (int ch = 0; ch < 4; ++ch) {
        const int b0 = ch * 64;
        __syncthreads();
        if (ch == 0) {
            const float4* W4 = (const float4*)(W + (size_t)i0 * 1280);
            float4* ws4 = (float4*)ws;
            for (int q = tid; q < 2560; q += NTHR) {
                int ic2 = q / 320, r = q - ic2 * 320;
                float c = (mode == 0) ? 0.1f : cs[ic2 * 10 + (r >> 5)];
                float4 wv = W4[q];
                ws4[q] = make_float4(wv.x * c, wv.y * c, wv.z * c, wv.w * c);
            }
        }
        for (int idx = tid; idx < 4096; idx += NTHR) {
            int ic2 = idx >> 9, k = (idx >> 6) & 7, b = idx & 63;
            float v = g_xT[((size_t)(i0 + ic2) * 8 + k) * BATCH + b0 + b];
            xb2f[((((ic2 * 4) + (k >> 1)) * 64 + b) << 1) | (k & 1)] = v;
        }
        __syncthreads();

        u64 accB[4][4];
#pragma unroll
        for (int bb = 0; bb < 4; ++bb)
#pragma unroll
            for (int cc = 0; cc < 4; ++cc) accB[bb][cc] = 0ULL;

        const u64* xb2d = (const u64*)xb2f;
        for (int ic2 = 0; ic2 < CPB; ++ic2) {
#pragma unroll
            for (int kp = 0; kp < 4; ++kp) {
                const u64* xp = xb2d + (ic2 * 4 + kp) * 64 + tx * 4;
                ulonglong2 xa = *(const ulonglong2*)xp;
                ulonglong2 xb = *(const ulonglong2*)(xp + 2);
#pragma unroll
                for (int cc = 0; cc < 4; ++cc) {
                    u64 w2 = *(const u64*)&ws[ic2 * 1280 + (ty * 4 + cc) * 8 + kp * 2];
                    FMA2(accB[0][cc], xa.x, w2);
                    FMA2(accB[1][cc], xa.y, w2);
                    FMA2(accB[2][cc], xb.x, w2);
                    FMA2(accB[3][cc], xb.y, w2);
                }
            }
        }

        float* outp = g_spart + (size_t)blockIdx.x * (COLS * BATCH);
#pragma unroll
        for (int cc = 0; cc < 4; ++cc) {
            int col = ty * 4 + cc;
            float4 r = make_float4(f2sum(accB[0][cc]), f2sum(accB[1][cc]),
                                   f2sum(accB[2][cc]), f2sum(accB[3][cc]));
            *(float4*)(outp + col * BATCH + b0 + tx * 4) = r;
        }
    }
}

// ---------------- squash: reduce 144 partials, write vB (+out) ----------------
__global__ __launch_bounds__(256) void squash_kernel(float* __restrict__ out, int write_out) {
    __shared__ float red[16][16][17];
    const int j  = blockIdx.x;
    const int b0 = blockIdx.y * 16;
    const int tid = threadIdx.x;
    const int b_loc = tid & 15, isg = tid >> 4;

    float acc[16];
#pragma unroll
    for (int d = 0; d < 16; ++d) acc[d] = 0.0f;
    for (int t = 0; t < 9; ++t) {
        int is = isg * 9 + t;
        const float* p = g_spart + ((size_t)is * COLS + j * 16) * BATCH + b0 + b_loc;
#pragma unroll
        for (int d = 0; d < 16; ++d) acc[d] += p[d * BATCH];
    }
#pragma unroll
    for (int d = 0; d < 16; ++d) red[isg][d][b_loc] = acc[d];
    __syncthreads();

    const int b2 = tid >> 4, d2 = tid & 15;
    float sv = 0.0f;
#pragma unroll
    for (int g = 0; g < 16; ++g) sv += red[g][d2][b2];

    float sq = sv * sv;
#pragma unroll
    for (int off = 8; off; off >>= 1)
        sq += __shfl_xor_sync(0xffffffffu, sq, off, 16);
    float coef = sq * rsqrtf(sq) / (1.0f + sq);
    float v = sv * coef;

    g_vB[(size_t)(b0 + b2) * COLS + j * 16 + d2] = v;
    if (write_out)
        out[(size_t)(b0 + b2) * COLS + j * 16 + d2] = v;
}

// ---------------- launch sequence ----------------
extern "C" void kernel_launch(void* const* d_in, const int* in_sizes, int n_in,
                              void* d_out, int out_size) {
    const float* x = (const float*)d_in[0];
    const float* W = (const float*)d_in[1];
    float* out = (float*)d_out;

    const int FSMEM = (10240 + 4096) * 4;   // 57344 B (phase-B union is the max)
    cudaFuncSetAttribute(f_kernel, cudaFuncAttributeMaxDynamicSharedMemorySize, FSMEM);

    transpose_x_kernel<<<dim3(KTOT / 32, BATCH / 32), dim3(32, 8)>>>(x);

    f_kernel<<<ISPLIT, NTHR, FSMEM>>>(W, 0);
    squash_kernel<<<dim3(10, 16), 256>>>(out, 0);
    f_kernel<<<ISPLIT, NTHR, FSMEM>>>(W, 1);
    squash_kernel<<<dim3(10, 16), 256>>>(out, 0);
    f_kernel<<<ISPLIT, NTHR, FSMEM>>>(W, 2);
    squash_kernel<<<dim3(10, 16), 256>>>(out, 1);
}

// round 6
// speedup vs baseline: 1.1626x; 1.1626x over previous
#include <cuda_runtime.h>

#define IN_NODES  1152
#define OUT_NODES 10
#define IN_DIM    8
#define OUT_DIM   16
#define BATCH     256
#define COLS      160
#define KTOT      (IN_NODES * IN_DIM)     // 9216
#define ISPLIT    144
#define CPB       8
#define NTHR      640

typedef unsigned long long u64;

// packed f32x2 FMA: acc.{lo,hi} += a.{lo,hi} * b.{lo,hi}
#define FMA2(acc, a, b) asm("fma.rn.f32x2 %0, %1, %2, %0;" : "+l"(acc) : "l"(a), "l"(b))

__device__ __forceinline__ float f2sum(u64 d) {
    float lo, hi;
    asm("mov.b64 {%0,%1}, %2;" : "=f"(lo), "=f"(hi) : "l"(d));
    return lo + hi;
}

// ---------------- device scratch ----------------
__device__ float g_xT   [KTOT * BATCH];            // x transposed [ik][b]
__device__ float g_spart[ISPLIT * COLS * BATCH];   // s partials [grp][col][b]
__device__ float g_vB   [BATCH * COLS];            // v batch-major [b][col]
__device__ float g_b    [IN_NODES * OUT_NODES];    // routing logits

// ---------------- transpose x [256][9216] -> xT [9216][256] ----------------
__global__ void transpose_x_kernel(const float* __restrict__ x) {
    __shared__ float tile[32][33];
    int ik0 = blockIdx.x * 32;
    int b0  = blockIdx.y * 32;
    int tx = threadIdx.x, ty = threadIdx.y;
#pragma unroll
    for (int r = 0; r < 32; r += 8)
        tile[ty + r][tx] = x[(size_t)(b0 + ty + r) * KTOT + ik0 + tx];
    __syncthreads();
#pragma unroll
    for (int r = 0; r < 32; r += 8)
        g_xT[(size_t)(ik0 + ty + r) * BATCH + b0 + tx] = tile[tx][ty + r];
}

// ---------------- fused: b-update + softmax + s-GEMM (f32x2, conflict-free) ----------------
// grid 144, 640 threads. Block owns capsules [i0,i0+8), full batch.
__global__ __launch_bounds__(NTHR, 1) void f_kernel(const float* __restrict__ W, int mode) {
    extern __shared__ float sm[];
    __shared__ float bsA[2][80];
    __shared__ float brow[80];
    __shared__ float cs[80];

    const int i0  = blockIdx.x * CPB;
    const int tid = threadIdx.x;

    if (mode > 0) {
        // ===== Phase A: T[i,k,col] = sum_b xT[ik,b]*vB[b,col]; f32x2 pairs over b =====
        float* vs = sm;          // [160 col][34] padded, b-contiguous
        float* xs = sm + 5440;   // [8 ic][8 k][32 b]
        const int w = tid >> 5, lane = tid & 31;
        const int ic = w & 7, kh = w >> 3;   // warps 0..15 active

        u64 acc2[4][5];
#pragma unroll
        for (int kk = 0; kk < 4; ++kk)
#pragma unroll
            for (int cc = 0; cc < 5; ++cc) acc2[kk][cc] = 0ULL;

        for (int cb = 0; cb < 8; ++cb) {
            const int b0 = cb * 32;
            __syncthreads();
            for (int idx = tid; idx < 5120; idx += NTHR) {
                int b = idx / 160, col = idx - b * 160;
                vs[col * 34 + b] = g_vB[(size_t)(b0 + b) * 160 + col];
            }
            for (int idx = tid; idx < 2048; idx += NTHR) {
                int ic2 = idx >> 8, k = (idx >> 5) & 7, b = idx & 31;
                xs[idx] = g_xT[((size_t)(i0 + ic2) * 8 + k) * BATCH + b0 + b];
            }
            __syncthreads();

            if (w < 16) {
#pragma unroll 4
                for (int b2 = 0; b2 < 16; ++b2) {
                    u64 xv[4];
#pragma unroll
                    for (int kk = 0; kk < 4; ++kk)
                        xv[kk] = *(const u64*)&xs[(ic * 8 + kh * 4 + kk) * 32 + 2 * b2];
#pragma unroll
                    for (int cc = 0; cc < 5; ++cc) {
                        u64 vv = *(const u64*)&vs[(cc * 32 + lane) * 34 + 2 * b2];
#pragma unroll
                        for (int kk = 0; kk < 4; ++kk)
                            FMA2(acc2[kk][cc], xv[kk], vv);
                    }
                }
            }
        }

        // contract with W -> delta-b partials; shfl reduce over 16-lane j groups
        if (w < 16) {
#pragma unroll
            for (int cc = 0; cc < 5; ++cc) {
                int col = cc * 32 + lane;
                float4 ww = *(const float4*)(W + ((size_t)(i0 + ic) * 160 + col) * 8 + kh * 4);
                float p = ww.x * f2sum(acc2[0][cc]) + ww.y * f2sum(acc2[1][cc])
                        + ww.z * f2sum(acc2[2][cc]) + ww.w * f2sum(acc2[3][cc]);
#pragma unroll
                for (int off = 8; off; off >>= 1)
                    p += __shfl_xor_sync(0xffffffffu, p, off, 16);
                if ((lane & 15) == 0)
                    bsA[kh][ic * 10 + cc * 2 + (lane >> 4)] = p;
            }
        }
        __syncthreads();

        if (tid < 80) {
            float bn = (bsA[0][tid] + bsA[1][tid]) * (1.0f / (float)BATCH);
            if (mode == 2) bn += g_b[i0 * OUT_NODES + tid];
            g_b[i0 * OUT_NODES + tid] = bn;
            brow[tid] = bn;
        }
        __syncthreads();
        if (tid < 8) {
            float m = -1e30f;
#pragma unroll
            for (int j = 0; j < 10; ++j) m = fmaxf(m, brow[tid * 10 + j]);
            float e[10], s = 0.0f;
#pragma unroll
            for (int j = 0; j < 10; ++j) { e[j] = __expf(brow[tid * 10 + j] - m); s += e[j]; }
            float inv = 1.0f / s;
#pragma unroll
            for (int j = 0; j < 10; ++j) cs[tid * 10 + j] = e[j] * inv;
        }
        __syncthreads();
    }

    // ===== Phase B: spart = sum_{ic,k} (c*W)[i,col,k]*xT[ik,b]; f32x2 pairs over k =====
    float* ws = sm;                     // [8 ic][160 col][8 k] scaled W
    u64*   xb = (u64*)(sm + 10240);     // [8 ic][4 kp][64 b] u64 = {x[2kp,b], x[2kp+1,b]}
    const int tx = tid & 15;            // b lanes; thread owns b = tx + 16q
    const int ty = tid >> 4;            // 0..39, 4 cols each

    for (int ch = 0; ch < 4; ++ch) {
        const int b0 = ch * 64;
        __syncthreads();
        if (ch == 0) {
            const float4* W4 = (const float4*)(W + (size_t)i0 * 1280);
            float4* ws4 = (float4*)ws;
            for (int q = tid; q < 2560; q += NTHR) {
                int ic2 = q / 320, r = q - ic2 * 320;
                float c = (mode == 0) ? 0.1f : cs[ic2 * 10 + (r >> 5)];
                float4 wv = W4[q];
                ws4[q] = make_float4(wv.x * c, wv.y * c, wv.z * c, wv.w * c);
            }
        }
        // stage x: k-pair interleave, one u64 per (ic, kp, b)
        float* xbf = (float*)xb;
        for (int idx = tid; idx < 4096; idx += NTHR) {
            int ic2 = idx >> 9, k = (idx >> 6) & 7, b = idx & 63;
            float v = g_xT[((size_t)(i0 + ic2) * 8 + k) * BATCH + b0 + b];
            xbf[((((ic2 * 4 + (k >> 1)) * 64) + b) << 1) | (k & 1)] = v;
        }
        __syncthreads();

        u64 accB[4][4];
#pragma unroll
        for (int q = 0; q < 4; ++q)
#pragma unroll
            for (int cc = 0; cc < 4; ++cc) accB[q][cc] = 0ULL;

#pragma unroll 2
        for (int ic2 = 0; ic2 < CPB; ++ic2) {
#pragma unroll
            for (int kp = 0; kp < 4; ++kp) {
                u64 xv[4];
#pragma unroll
                for (int q = 0; q < 4; ++q)
                    xv[q] = xb[(ic2 * 4 + kp) * 64 + tx + 16 * q];   // conflict-free
#pragma unroll
                for (int cc = 0; cc < 4; ++cc) {
                    u64 w2 = *(const u64*)&ws[ic2 * 1280 + (ty * 4 + cc) * 8 + kp * 2];
                    FMA2(accB[0][cc], xv[0], w2);
                    FMA2(accB[1][cc], xv[1], w2);
                    FMA2(accB[2][cc], xv[2], w2);
                    FMA2(accB[3][cc], xv[3], w2);
                }
            }
        }

        float* outp = g_spart + (size_t)blockIdx.x * (COLS * BATCH);
#pragma unroll
        for (int cc = 0; cc < 4; ++cc) {
            int col = ty * 4 + cc;
#pragma unroll
            for (int q = 0; q < 4; ++q)
                outp[col * BATCH + b0 + tx + 16 * q] = f2sum(accB[q][cc]);
        }
    }
}

// ---------------- squash: reduce 144 partials, write vB (+out) ----------------
__global__ __launch_bounds__(256) void squash_kernel(float* __restrict__ out, int write_out) {
    __shared__ float red[16][16][17];
    const int j  = blockIdx.x;
    const int b0 = blockIdx.y * 16;
    const int tid = threadIdx.x;
    const int b_loc = tid & 15, isg = tid >> 4;

    float acc[16];
#pragma unroll
    for (int d = 0; d < 16; ++d) acc[d] = 0.0f;
    for (int t = 0; t < 9; ++t) {
        int is = isg * 9 + t;
        const float* p = g_spart + ((size_t)is * COLS + j * 16) * BATCH + b0 + b_loc;
#pragma unroll
        for (int d = 0; d < 16; ++d) acc[d] += p[d * BATCH];
    }
#pragma unroll
    for (int d = 0; d < 16; ++d) red[isg][d][b_loc] = acc[d];
    __syncthreads();

    const int b2 = tid >> 4, d2 = tid & 15;
    float sv = 0.0f;
#pragma unroll
    for (int g = 0; g < 16; ++g) sv += red[g][d2][b2];

    float sq = sv * sv;
#pragma unroll
    for (int off = 8; off; off >>= 1)
        sq += __shfl_xor_sync(0xffffffffu, sq, off, 16);
    float coef = sq * rsqrtf(sq) / (1.0f + sq);
    float v = sv * coef;

    g_vB[(size_t)(b0 + b2) * COLS + j * 16 + d2] = v;
    if (write_out)
        out[(size_t)(b0 + b2) * COLS + j * 16 + d2] = v;
}

// ---------------- launch sequence ----------------
extern "C" void kernel_launch(void* const* d_in, const int* in_sizes, int n_in,
                              void* d_out, int out_size) {
    const float* x = (const float*)d_in[0];
    const float* W = (const float*)d_in[1];
    float* out = (float*)d_out;

    const int FSMEM = (10240 + 4096) * 4;   // 57344 B
    cudaFuncSetAttribute(f_kernel, cudaFuncAttributeMaxDynamicSharedMemorySize, FSMEM);

    transpose_x_kernel<<<dim3(KTOT / 32, BATCH / 32), dim3(32, 8)>>>(x);

    f_kernel<<<ISPLIT, NTHR, FSMEM>>>(W, 0);
    squash_kernel<<<dim3(10, 16), 256>>>(out, 0);
    f_kernel<<<ISPLIT, NTHR, FSMEM>>>(W, 1);
    squash_kernel<<<dim3(10, 16), 256>>>(out, 0);
    f_kernel<<<ISPLIT, NTHR, FSMEM>>>(W, 2);
    squash_kernel<<<dim3(10, 16), 256>>>(out, 1);
}

// round 7
// speedup vs baseline: 1.2656x; 1.0886x over previous
#include <cuda_runtime.h>

#define IN_NODES  1152
#define OUT_NODES 10
#define IN_DIM    8
#define OUT_DIM   16
#define BATCH     256
#define COLS      160
#define KTOT      (IN_NODES * IN_DIM)     // 9216
#define ISPLIT    144
#define CPB       8
#define NTHR      512

typedef unsigned long long u64;

// packed f32x2 FMA: acc.{lo,hi} += a.{lo,hi} * b.{lo,hi}
#define FMA2(acc, a, b) asm("fma.rn.f32x2 %0, %1, %2, %0;" : "+l"(acc) : "l"(a), "l"(b))

__device__ __forceinline__ float f2sum(u64 d) {
    float lo, hi;
    asm("mov.b64 {%0,%1}, %2;" : "=f"(lo), "=f"(hi) : "l"(d));
    return lo + hi;
}

// ---------------- device scratch ----------------
__device__ float g_xT   [KTOT * BATCH];            // x transposed [ik][b]
__device__ float g_spart[ISPLIT * COLS * BATCH];   // s partials [grp][col][b]
__device__ float g_vB   [BATCH * COLS];            // v batch-major [b][col]
__device__ float g_b    [IN_NODES * OUT_NODES];    // routing logits

// ---------------- transpose x [256][9216] -> xT [9216][256] ----------------
__global__ void transpose_x_kernel(const float* __restrict__ x) {
    __shared__ float tile[32][33];
    int ik0 = blockIdx.x * 32;
    int b0  = blockIdx.y * 32;
    int tx = threadIdx.x, ty = threadIdx.y;
#pragma unroll
    for (int r = 0; r < 32; r += 8)
        tile[ty + r][tx] = x[(size_t)(b0 + ty + r) * KTOT + ik0 + tx];
    __syncthreads();
#pragma unroll
    for (int r = 0; r < 32; r += 8)
        g_xT[(size_t)(ik0 + ty + r) * BATCH + b0 + tx] = tile[tx][ty + r];
}

// ---------------- fused: b-update + softmax + s-GEMM (f32x2) ----------------
// grid 144, 512 threads. Block owns capsules [i0,i0+8), full batch.
// Phase A smem: vs[160][66] + xs[8][8][64] = 14656 fl. Phase B: ws 10240 + xb 4096 fl.
__global__ __launch_bounds__(NTHR, 1) void f_kernel(const float* __restrict__ W, int mode) {
    extern __shared__ float sm[];
    __shared__ float bsA[2][80];
    __shared__ float brow[80];
    __shared__ float cs[80];

    const int i0  = blockIdx.x * CPB;
    const int tid = threadIdx.x;

    if (mode > 0) {
        // ===== Phase A: T[i,k,col] = sum_b xT[ik,b]*vB[b,col]; 8k x 5col tile =====
        float* vs = sm;           // [160 col][66] padded (u64 stride 33 -> conflict-free)
        float* xs = sm + 10560;   // [8 ic][8 k][64 b]
        const int w = tid >> 5, lane = tid & 31;
        const int ic = w & 7, bh = w >> 3;   // b-half within each 64-b chunk

        u64 acc2[8][5];
#pragma unroll
        for (int kk = 0; kk < 8; ++kk)
#pragma unroll
            for (int cc = 0; cc < 5; ++cc) acc2[kk][cc] = 0ULL;

        for (int cb = 0; cb < 4; ++cb) {
            const int b0 = cb * 64;
            __syncthreads();
            for (int idx = tid; idx < 10240; idx += NTHR) {
                int b = idx / 160, col = idx - b * 160;
                vs[col * 66 + b] = g_vB[(size_t)(b0 + b) * 160 + col];
            }
            for (int idx = tid; idx < 4096; idx += NTHR) {
                int ic2 = idx >> 9, k = (idx >> 6) & 7, b = idx & 63;
                xs[idx] = g_xT[((size_t)(i0 + ic2) * 8 + k) * BATCH + b0 + b];
            }
            __syncthreads();

#pragma unroll 4
            for (int b2 = 0; b2 < 16; ++b2) {
                u64 xv[8];
#pragma unroll
                for (int kk = 0; kk < 8; ++kk)
                    xv[kk] = *(const u64*)&xs[(ic * 8 + kk) * 64 + bh * 32 + 2 * b2];
#pragma unroll
                for (int cc = 0; cc < 5; ++cc) {
                    u64 vv = *(const u64*)&vs[(cc * 32 + lane) * 66 + bh * 32 + 2 * b2];
#pragma unroll
                    for (int kk = 0; kk < 8; ++kk)
                        FMA2(acc2[kk][cc], xv[kk], vv);
                }
            }
        }

        // contract with W (all 8 k) -> delta-b partials; shfl reduce over 16-lane j groups
#pragma unroll
        for (int cc = 0; cc < 5; ++cc) {
            int col = cc * 32 + lane;
            const float4* w4 = (const float4*)(W + ((size_t)(i0 + ic) * 160 + col) * 8);
            float4 wa = w4[0], wb = w4[1];
            float p = wa.x * f2sum(acc2[0][cc]) + wa.y * f2sum(acc2[1][cc])
                    + wa.z * f2sum(acc2[2][cc]) + wa.w * f2sum(acc2[3][cc])
                    + wb.x * f2sum(acc2[4][cc]) + wb.y * f2sum(acc2[5][cc])
                    + wb.z * f2sum(acc2[6][cc]) + wb.w * f2sum(acc2[7][cc]);
#pragma unroll
            for (int off = 8; off; off >>= 1)
                p += __shfl_xor_sync(0xffffffffu, p, off, 16);
            if ((lane & 15) == 0)
                bsA[bh][ic * 10 + cc * 2 + (lane >> 4)] = p;
        }
        __syncthreads();

        if (tid < 80) {
            float bn = (bsA[0][tid] + bsA[1][tid]) * (1.0f / (float)BATCH);
            if (mode == 2) bn += g_b[i0 * OUT_NODES + tid];
            g_b[i0 * OUT_NODES + tid] = bn;
            brow[tid] = bn;
        }
        __syncthreads();
        if (tid < 8) {
            float m = -1e30f;
#pragma unroll
            for (int j = 0; j < 10; ++j) m = fmaxf(m, brow[tid * 10 + j]);
            float e[10], s = 0.0f;
#pragma unroll
            for (int j = 0; j < 10; ++j) { e[j] = __expf(brow[tid * 10 + j] - m); s += e[j]; }
            float inv = 1.0f / s;
#pragma unroll
            for (int j = 0; j < 10; ++j) cs[tid * 10 + j] = e[j] * inv;
        }
        __syncthreads();
    }

    // ===== Phase B: spart = sum_{ic,k} (c*W)[i,col,k]*xT[ik,b]; f32x2 pairs over k =====
    float* ws = sm;                     // [8 ic][160 col][8 k] scaled W
    u64*   xb = (u64*)(sm + 10240);     // [8 ic][4 kp][64 b] u64 = {x[2kp,b], x[2kp+1,b]}
    const int tx = tid & 15;            // b lanes; thread owns b = tx + 16q
    const int ty = tid >> 4;            // 0..31, 5 cols each

    for (int ch = 0; ch < 4; ++ch) {
        const int b0 = ch * 64;
        __syncthreads();
        if (ch == 0) {
            const float4* W4 = (const float4*)(W + (size_t)i0 * 1280);
            float4* ws4 = (float4*)ws;
            for (int q = tid; q < 2560; q += NTHR) {
                int ic2 = q / 320, r = q - ic2 * 320;
                float c = (mode == 0) ? 0.1f : cs[ic2 * 10 + (r >> 5)];
                float4 wv = W4[q];
                ws4[q] = make_float4(wv.x * c, wv.y * c, wv.z * c, wv.w * c);
            }
        }
        // stage x: k-pair interleave, one u64 per (ic, kp, b)
        float* xbf = (float*)xb;
        for (int idx = tid; idx < 4096; idx += NTHR) {
            int ic2 = idx >> 9, k = (idx >> 6) & 7, b = idx & 63;
            float v = g_xT[((size_t)(i0 + ic2) * 8 + k) * BATCH + b0 + b];
            xbf[((((ic2 * 4 + (k >> 1)) * 64) + b) << 1) | (k & 1)] = v;
        }
        __syncthreads();

        u64 accB[4][5];
#pragma unroll
        for (int q = 0; q < 4; ++q)
#pragma unroll
            for (int cc = 0; cc < 5; ++cc) accB[q][cc] = 0ULL;

#pragma unroll 2
        for (int ic2 = 0; ic2 < CPB; ++ic2) {
#pragma unroll
            for (int kp = 0; kp < 4; ++kp) {
                u64 xv[4];
#pragma unroll
                for (int q = 0; q < 4; ++q)
                    xv[q] = xb[(ic2 * 4 + kp) * 64 + tx + 16 * q];   // conflict-free
#pragma unroll
                for (int cc = 0; cc < 5; ++cc) {
                    u64 w2 = *(const u64*)&ws[ic2 * 1280 + (ty * 5 + cc) * 8 + kp * 2];
                    FMA2(accB[0][cc], xv[0], w2);
                    FMA2(accB[1][cc], xv[1], w2);
                    FMA2(accB[2][cc], xv[2], w2);
                    FMA2(accB[3][cc], xv[3], w2);
                }
            }
        }

        float* outp = g_spart + (size_t)blockIdx.x * (COLS * BATCH);
#pragma unroll
        for (int cc = 0; cc < 5; ++cc) {
            int col = ty * 5 + cc;
#pragma unroll
            for (int q = 0; q < 4; ++q)
                outp[col * BATCH + b0 + tx + 16 * q] = f2sum(accB[q][cc]);
        }
    }
}

// ---------------- squash: reduce 144 partials, write vB (+out) ----------------
__global__ __launch_bounds__(256) void squash_kernel(float* __restrict__ out, int write_out) {
    __shared__ float red[16][16][17];
    const int j  = blockIdx.x;
    const int b0 = blockIdx.y * 16;
    const int tid = threadIdx.x;
    const int b_loc = tid & 15, isg = tid >> 4;

    float acc[16];
#pragma unroll
    for (int d = 0; d < 16; ++d) acc[d] = 0.0f;
    for (int t = 0; t < 9; ++t) {
        int is = isg * 9 + t;
        const float* p = g_spart + ((size_t)is * COLS + j * 16) * BATCH + b0 + b_loc;
#pragma unroll
        for (int d = 0; d < 16; ++d) acc[d] += p[d * BATCH];
    }
#pragma unroll
    for (int d = 0; d < 16; ++d) red[isg][d][b_loc] = acc[d];
    __syncthreads();

    const int b2 = tid >> 4, d2 = tid & 15;
    float sv = 0.0f;
#pragma unroll
    for (int g = 0; g < 16; ++g) sv += red[g][d2][b2];

    float sq = sv * sv;
#pragma unroll
    for (int off = 8; off; off >>= 1)
        sq += __shfl_xor_sync(0xffffffffu, sq, off, 16);
    float coef = sq * rsqrtf(sq) / (1.0f + sq);
    float v = sv * coef;

    g_vB[(size_t)(b0 + b2) * COLS + j * 16 + d2] = v;
    if (write_out)
        out[(size_t)(b0 + b2) * COLS + j * 16 + d2] = v;
}

// ---------------- launch sequence ----------------
extern "C" void kernel_launch(void* const* d_in, const int* in_sizes, int n_in,
                              void* d_out, int out_size) {
    const float* x = (const float*)d_in[0];
    const float* W = (const float*)d_in[1];
    float* out = (float*)d_out;

    const int FSMEM = 14656 * 4;   // 58624 B (phase-A union is the max)
    cudaFuncSetAttribute(f_kernel, cudaFuncAttributeMaxDynamicSharedMemorySize, FSMEM);

    transpose_x_kernel<<<dim3(KTOT / 32, BATCH / 32), dim3(32, 8)>>>(x);

    f_kernel<<<ISPLIT, NTHR, FSMEM>>>(W, 0);
    squash_kernel<<<dim3(10, 16), 256>>>(out, 0);
    f_kernel<<<ISPLIT, NTHR, FSMEM>>>(W, 1);
    squash_kernel<<<dim3(10, 16), 256>>>(out, 0);
    f_kernel<<<ISPLIT, NTHR, FSMEM>>>(W, 2);
    squash_kernel<<<dim3(10, 16), 256>>>(out, 1);
}